// round 3
// baseline (speedup 1.0000x reference)
#include <cuda_runtime.h>
#include <math.h>

// ---------------------------------------------------------------------------
// SpectroTFDecoder: pre-LN transformer decoder layer, fp32 (f32x2-packed math).
// B=4, T=1024, D=1024, H=16, DH=64, DFF=4096.
// Input order: 0 x, 1 src_x, 2 mask, 3 src_mask, 4-9 ln{1,2,3}_{g,b},
// 10-17 weights (sa_wq,sa_wk,sa_wv,sa_wo,ca_wq,ca_wk,ca_wv,ca_wo),
// 18-25 biases (same order), 26-29 ff_w1,ff_b1,ff_w2,ff_b2.
// ---------------------------------------------------------------------------

#define D_MODEL 1024
#define BATCH   4
#define TSEQ    1024
#define N_ROWS  (BATCH * TSEQ)
#define NHEAD   16
#define DHEAD   64
#define DFF_    4096
#define LN_EPS  1e-6f

typedef unsigned long long ull;

__device__ __forceinline__ void fma2(ull& d, ull a, ull b) {
    asm("fma.rn.f32x2 %0, %1, %2, %0;" : "+l"(d) : "l"(a), "l"(b));
}
__device__ __forceinline__ void mul2(ull& d, ull a) {
    asm("mul.rn.f32x2 %0, %0, %1;" : "+l"(d) : "l"(a));
}
__device__ __forceinline__ ull pack2(float x, float y) {
    ull r; asm("mov.b64 %0, {%1, %2};" : "=l"(r) : "f"(x), "f"(y)); return r;
}
__device__ __forceinline__ float2 unpack2(ull v) {
    float2 r; asm("mov.b64 {%0, %1}, %2;" : "=f"(r.x), "=f"(r.y) : "l"(v)); return r;
}

// Scratch
__device__ float g_h  [N_ROWS * D_MODEL];
__device__ float g_q  [N_ROWS * D_MODEL];
__device__ float g_k  [N_ROWS * D_MODEL];
__device__ float g_v  [N_ROWS * D_MODEL];
__device__ float g_ctx[N_ROWS * D_MODEL];
__device__ float g_x1 [N_ROWS * D_MODEL];
__device__ float g_x2 [N_ROWS * D_MODEL];
__device__ float g_ff [N_ROWS * DFF_];

// ---------------------------------------------------------------------------
// LayerNorm
// ---------------------------------------------------------------------------
__global__ __launch_bounds__(256)
void ln_kernel(const float* __restrict__ x, const float* __restrict__ g,
               const float* __restrict__ bta, float* __restrict__ o)
{
    const int row = blockIdx.x;
    const int t = threadIdx.x;
    const float* xr = x + (size_t)row * D_MODEL;
    float4 xv = *(const float4*)(xr + t * 4);

    float s = xv.x + xv.y + xv.z + xv.w;
    __shared__ float red[8];
    #pragma unroll
    for (int off = 16; off > 0; off >>= 1) s += __shfl_xor_sync(~0u, s, off);
    if ((t & 31) == 0) red[t >> 5] = s;
    __syncthreads();
    float tot = 0.f;
    #pragma unroll
    for (int i = 0; i < 8; i++) tot += red[i];
    const float mu = tot * (1.f / 1024.f);

    const float dx0 = xv.x - mu, dx1 = xv.y - mu, dx2 = xv.z - mu, dx3 = xv.w - mu;
    float sq = dx0*dx0 + dx1*dx1 + dx2*dx2 + dx3*dx3;
    #pragma unroll
    for (int off = 16; off > 0; off >>= 1) sq += __shfl_xor_sync(~0u, sq, off);
    __syncthreads();
    if ((t & 31) == 0) red[t >> 5] = sq;
    __syncthreads();
    float tot2 = 0.f;
    #pragma unroll
    for (int i = 0; i < 8; i++) tot2 += red[i];
    const float sigma = sqrtf(tot2 * (1.f / 1024.f));
    const float inv = 1.f / (sigma + LN_EPS);

    float4 gv = *(const float4*)(g + t * 4);
    float4 bv = *(const float4*)(bta + t * 4);
    float4 ov;
    ov.x = dx0 * inv * gv.x + bv.x;
    ov.y = dx1 * inv * gv.y + bv.y;
    ov.z = dx2 * inv * gv.z + bv.z;
    ov.w = dx3 * inv * gv.w + bv.w;
    *(float4*)(o + (size_t)row * D_MODEL + t * 4) = ov;
}

// ---------------------------------------------------------------------------
// SGEMM, f32x2-packed. C = A@W + bias (+res), optional ReLU.
// 128x128 tile, BK=8, 256 threads, 8x8 micro-tile held as 8x4 f32x2 pairs.
// A stored DUPLICATED in smem ({a,a} pairs) so broadcast operands are direct
// LDS.64 loads; B pairs load directly from natural layout.
// ---------------------------------------------------------------------------
template<bool RELU, bool RES>
__global__ __launch_bounds__(256, 2)
void sgemm_kernel(const float* __restrict__ A, const float* __restrict__ W,
                  const float* __restrict__ bias, const float* __restrict__ res,
                  float* __restrict__ C, int M, int N, int K)
{
    __shared__ float As2[2][8][256];   // duplicated A: col 2*r and 2*r+1 hold a[r]
    __shared__ float Bs [2][8][128];
    const int tid = threadIdx.x;
    const int bm = blockIdx.y * 128;
    const int bn = blockIdx.x * 128;

    const int arow = tid >> 1;            // 0..127
    const int acol = (tid & 1) * 4;       // 0 or 4
    const int brow = tid >> 5;            // 0..7
    const int bcol = (tid & 31) * 4;      // 0..124

    const float* Aptr = A + (size_t)(bm + arow) * K + acol;
    const float* Bptr = W + (size_t)brow * N + bn + bcol;

    const int ty = tid >> 4;
    const int tx = tid & 15;
    const int crow = ty * 8;
    const int c0 = tx * 4;
    const int c1 = 64 + tx * 4;

    ull acc[8][4];
    #pragma unroll
    for (int i = 0; i < 8; i++)
        #pragma unroll
        for (int j = 0; j < 4; j++) acc[i][j] = 0ull;

    // prologue: stage 0
    {
        float4 a4 = *(const float4*)Aptr;
        float4 b4 = *(const float4*)Bptr;
        *(ull*)&As2[0][acol + 0][2 * arow] = pack2(a4.x, a4.x);
        *(ull*)&As2[0][acol + 1][2 * arow] = pack2(a4.y, a4.y);
        *(ull*)&As2[0][acol + 2][2 * arow] = pack2(a4.z, a4.z);
        *(ull*)&As2[0][acol + 3][2 * arow] = pack2(a4.w, a4.w);
        *(float4*)&Bs[0][brow][bcol] = b4;
    }
    __syncthreads();

    const int nk = K >> 3;
    for (int kt = 0; kt < nk; kt++) {
        const int cur = kt & 1;
        const int nxt = cur ^ 1;
        float4 a4n, b4n;
        const bool more = (kt + 1 < nk);
        if (more) {
            a4n = *(const float4*)(Aptr + (size_t)(kt + 1) * 8);
            b4n = *(const float4*)(Bptr + (size_t)(kt + 1) * 8 * N);
        }
        #pragma unroll
        for (int k = 0; k < 8; k++) {
            const ulonglong2* ap = (const ulonglong2*)&As2[cur][k][2 * crow];
            ulonglong2 aA = ap[0], aB = ap[1], aC = ap[2], aD = ap[3];
            ulonglong2 b0 = *(const ulonglong2*)&Bs[cur][k][c0];
            ulonglong2 b1 = *(const ulonglong2*)&Bs[cur][k][c1];
            ull av[8] = {aA.x, aA.y, aB.x, aB.y, aC.x, aC.y, aD.x, aD.y};
            ull bv[4] = {b0.x, b0.y, b1.x, b1.y};
            #pragma unroll
            for (int i = 0; i < 8; i++) {
                fma2(acc[i][0], av[i], bv[0]);
                fma2(acc[i][1], av[i], bv[1]);
                fma2(acc[i][2], av[i], bv[2]);
                fma2(acc[i][3], av[i], bv[3]);
            }
        }
        if (more) {
            *(ull*)&As2[nxt][acol + 0][2 * arow] = pack2(a4n.x, a4n.x);
            *(ull*)&As2[nxt][acol + 1][2 * arow] = pack2(a4n.y, a4n.y);
            *(ull*)&As2[nxt][acol + 2][2 * arow] = pack2(a4n.z, a4n.z);
            *(ull*)&As2[nxt][acol + 3][2 * arow] = pack2(a4n.w, a4n.w);
            *(float4*)&Bs[nxt][brow][bcol] = b4n;
        }
        __syncthreads();
    }

    // epilogue
    float bia[8];
    #pragma unroll
    for (int j = 0; j < 4; j++) {
        bia[j]     = bias[bn + c0 + j];
        bia[4 + j] = bias[bn + c1 + j];
    }
    #pragma unroll
    for (int i = 0; i < 8; i++) {
        const int row = bm + crow + i;
        float* cp = C + (size_t)row * N + bn;
        float2 u0 = unpack2(acc[i][0]);
        float2 u1 = unpack2(acc[i][1]);
        float2 u2 = unpack2(acc[i][2]);
        float2 u3 = unpack2(acc[i][3]);
        float v[8] = {u0.x, u0.y, u1.x, u1.y, u2.x, u2.y, u3.x, u3.y};
        #pragma unroll
        for (int j = 0; j < 8; j++) v[j] += bia[j];
        if (RELU) {
            #pragma unroll
            for (int j = 0; j < 8; j++) v[j] = fmaxf(v[j], 0.f);
        }
        if (RES) {
            const float* rp = res + (size_t)row * N + bn;
            float4 r0 = *(const float4*)(rp + c0);
            float4 r1 = *(const float4*)(rp + c1);
            v[0] += r0.x; v[1] += r0.y; v[2] += r0.z; v[3] += r0.w;
            v[4] += r1.x; v[5] += r1.y; v[6] += r1.z; v[7] += r1.w;
        }
        float4 o0 = {v[0], v[1], v[2], v[3]};
        float4 o1 = {v[4], v[5], v[6], v[7]};
        *(float4*)(cp + c0) = o0;
        *(float4*)(cp + c1) = o1;
    }
}

// ---------------------------------------------------------------------------
// Flash attention, fp32 via f32x2. Block = 64 q-rows x 1 head x 1 batch.
// Thread (qrow=tid>>2, sub=tid&3) owns CONTIGUOUS keys/dims sub*16..sub*16+15.
// Smem: Qs2 (q duplicated pairs), Ps2 (p duplicated pairs), KVs (K transposed
// for S-loop, then V natural for PV-loop).
// ---------------------------------------------------------------------------
#define QS2S 132   // dup row stride (floats): 64 dup'd values + pad, 16B-aligned
#define KVSS 68    // K/V row stride
#define ATTN_SMEM ((2 * 64 * QS2S + 64 * KVSS) * (int)sizeof(float))

__global__ __launch_bounds__(256)
void attn_kernel(const float* __restrict__ Q, const float* __restrict__ Kv,
                 const float* __restrict__ Vv, float* __restrict__ O,
                 int causal)
{
    const int qt = blockIdx.x;
    const int h  = blockIdx.y;
    const int b  = blockIdx.z;
    const int tid = threadIdx.x;
    const int qrow = tid >> 2;
    const int sub  = tid & 3;

    const size_t base = ((size_t)b * TSEQ) * D_MODEL + (size_t)h * DHEAD;

    extern __shared__ float sm[];
    float* Qs2 = sm;                    // [64][QS2S] duplicated q
    float* Ps2 = sm + 64 * QS2S;        // [64][QS2S] duplicated p
    float* KVs = sm + 2 * 64 * QS2S;    // [64][KVSS] Kt then V

    const int r  = tid >> 2;            // staging row (key or q row)
    const int cc = (tid & 3) * 16;      // staging dim offset

    // load Q tile, scaled, duplicated
    {
        const float* src = Q + base + (size_t)(qt * 64 + r) * D_MODEL + cc;
        #pragma unroll
        for (int c = 0; c < 16; c += 4) {
            float4 v4 = *(const float4*)(src + c);
            float4 d0 = {v4.x * 0.125f, v4.x * 0.125f, v4.y * 0.125f, v4.y * 0.125f};
            float4 d1 = {v4.z * 0.125f, v4.z * 0.125f, v4.w * 0.125f, v4.w * 0.125f};
            *(float4*)&Qs2[r * QS2S + 2 * (cc + c)]     = d0;
            *(float4*)&Qs2[r * QS2S + 2 * (cc + c) + 4] = d1;
        }
    }

    float m = -INFINITY, l = 0.f;
    ull acc2[8];
    #pragma unroll
    for (int i = 0; i < 8; i++) acc2[i] = 0ull;

    const int ktEnd = causal ? qt : (TSEQ / 64 - 1);
    const int qg = qt * 64 + qrow;

    for (int kt = 0; kt <= ktEnd; kt++) {
        __syncthreads();   // prior PV reads done
        // store K TRANSPOSED: Kt[dd][key]
        {
            const float* src = Kv + base + (size_t)(kt * 64 + r) * D_MODEL + cc;
            #pragma unroll
            for (int c = 0; c < 16; c += 4) {
                float4 v4 = *(const float4*)(src + c);
                KVs[(cc + c + 0) * KVSS + r] = v4.x;
                KVs[(cc + c + 1) * KVSS + r] = v4.y;
                KVs[(cc + c + 2) * KVSS + r] = v4.z;
                KVs[(cc + c + 3) * KVSS + r] = v4.w;
            }
        }
        __syncthreads();

        // S = Q @ K^T : keys sub*16..sub*16+15, packed pairs
        ull s2[8];
        #pragma unroll
        for (int j = 0; j < 8; j++) s2[j] = 0ull;
        const float* qp = &Qs2[qrow * QS2S];
        const float* kp = &KVs[sub * 16];
        #pragma unroll 16
        for (int dd = 0; dd < 64; dd++) {
            ull qv = *(const ull*)(qp + 2 * dd);
            const ulonglong2* kr = (const ulonglong2*)(kp + dd * KVSS);
            ulonglong2 k0 = kr[0], k1 = kr[1], k2 = kr[2], k3 = kr[3];
            fma2(s2[0], qv, k0.x); fma2(s2[1], qv, k0.y);
            fma2(s2[2], qv, k1.x); fma2(s2[3], qv, k1.y);
            fma2(s2[4], qv, k2.x); fma2(s2[5], qv, k2.y);
            fma2(s2[6], qv, k3.x); fma2(s2[7], qv, k3.y);
        }

        // unpack, mask, online softmax
        float sf[16];
        #pragma unroll
        for (int j = 0; j < 8; j++) {
            float2 u = unpack2(s2[j]);
            sf[2 * j] = u.x; sf[2 * j + 1] = u.y;
        }
        float tmax = -INFINITY;
        const bool diag = causal && (kt == qt);
        const int kbase = kt * 64 + sub * 16;
        #pragma unroll
        for (int j = 0; j < 16; j++) {
            if (diag && (kbase + j) > qg) sf[j] = -INFINITY;
            tmax = fmaxf(tmax, sf[j]);
        }
        tmax = fmaxf(tmax, __shfl_xor_sync(~0u, tmax, 1));
        tmax = fmaxf(tmax, __shfl_xor_sync(~0u, tmax, 2));
        const float mnew = fmaxf(m, tmax);
        const float corr = __expf(m - mnew);
        float p[16];
        float lsum = 0.f;
        #pragma unroll
        for (int j = 0; j < 16; j++) {
            p[j] = __expf(sf[j] - mnew);
            lsum += p[j];
        }
        // store duplicated P
        {
            float* pd = &Ps2[qrow * QS2S + 2 * (sub * 16)];
            #pragma unroll
            for (int j = 0; j < 16; j += 2) {
                float4 d = {p[j], p[j], p[j + 1], p[j + 1]};
                *(float4*)(pd + 2 * j) = d;
            }
        }
        lsum += __shfl_xor_sync(~0u, lsum, 1);
        lsum += __shfl_xor_sync(~0u, lsum, 2);
        l = l * corr + lsum;
        m = mnew;
        const ull corr2 = pack2(corr, corr);
        #pragma unroll
        for (int i = 0; i < 8; i++) mul2(acc2[i], corr2);
        __syncthreads();   // K reads + Ps writes done

        // store V natural: V[key][dh]
        {
            const float* src = Vv + base + (size_t)(kt * 64 + r) * D_MODEL + cc;
            #pragma unroll
            for (int c = 0; c < 16; c += 4) {
                float4 v4 = *(const float4*)(src + c);
                *(float4*)&KVs[r * KVSS + cc + c] = v4;
            }
        }
        __syncthreads();

        // acc += P @ V : dims sub*16..sub*16+15
        const float* pp = &Ps2[qrow * QS2S];
        const float* vp0 = &KVs[sub * 16];
        #pragma unroll 16
        for (int kk = 0; kk < 64; kk++) {
            ull pv = *(const ull*)(pp + 2 * kk);
            const ulonglong2* vr = (const ulonglong2*)(vp0 + kk * KVSS);
            ulonglong2 v0 = vr[0], v1 = vr[1], v2 = vr[2], v3 = vr[3];
            fma2(acc2[0], pv, v0.x); fma2(acc2[1], pv, v0.y);
            fma2(acc2[2], pv, v1.x); fma2(acc2[3], pv, v1.y);
            fma2(acc2[4], pv, v2.x); fma2(acc2[5], pv, v2.y);
            fma2(acc2[6], pv, v3.x); fma2(acc2[7], pv, v3.y);
        }
    }

    const float inv = 1.f / l;
    float* op = O + base + (size_t)(qt * 64 + qrow) * D_MODEL + sub * 16;
    #pragma unroll
    for (int i = 0; i < 4; i++) {
        float2 ua = unpack2(acc2[2 * i]);
        float2 ub = unpack2(acc2[2 * i + 1]);
        float4 o4 = {ua.x * inv, ua.y * inv, ub.x * inv, ub.y * inv};
        *(float4*)(op + 4 * i) = o4;
    }
}

// ---------------------------------------------------------------------------
// Host orchestration
// ---------------------------------------------------------------------------
extern "C" void kernel_launch(void* const* d_in, const int* in_sizes, int n_in,
                              void* d_out, int out_size)
{
    (void)in_sizes; (void)n_in; (void)out_size;
    const float* x     = (const float*)d_in[0];
    const float* src_x = (const float*)d_in[1];
    const float* ln1_g = (const float*)d_in[4];
    const float* ln1_b = (const float*)d_in[5];
    const float* ln2_g = (const float*)d_in[6];
    const float* ln2_b = (const float*)d_in[7];
    const float* ln3_g = (const float*)d_in[8];
    const float* ln3_b = (const float*)d_in[9];
    const float* sa_wq = (const float*)d_in[10];
    const float* sa_wk = (const float*)d_in[11];
    const float* sa_wv = (const float*)d_in[12];
    const float* sa_wo = (const float*)d_in[13];
    const float* ca_wq = (const float*)d_in[14];
    const float* ca_wk = (const float*)d_in[15];
    const float* ca_wv = (const float*)d_in[16];
    const float* ca_wo = (const float*)d_in[17];
    const float* sa_bq = (const float*)d_in[18];
    const float* sa_bk = (const float*)d_in[19];
    const float* sa_bv = (const float*)d_in[20];
    const float* sa_bo = (const float*)d_in[21];
    const float* ca_bq = (const float*)d_in[22];
    const float* ca_bk = (const float*)d_in[23];
    const float* ca_bv = (const float*)d_in[24];
    const float* ca_bo = (const float*)d_in[25];
    const float* ff_w1 = (const float*)d_in[26];
    const float* ff_b1 = (const float*)d_in[27];
    const float* ff_w2 = (const float*)d_in[28];
    const float* ff_b2 = (const float*)d_in[29];
    float* out = (float*)d_out;

    float *h, *q, *k, *v, *ctx, *x1, *x2, *ff;
    cudaGetSymbolAddress((void**)&h,   g_h);
    cudaGetSymbolAddress((void**)&q,   g_q);
    cudaGetSymbolAddress((void**)&k,   g_k);
    cudaGetSymbolAddress((void**)&v,   g_v);
    cudaGetSymbolAddress((void**)&ctx, g_ctx);
    cudaGetSymbolAddress((void**)&x1,  g_x1);
    cudaGetSymbolAddress((void**)&x2,  g_x2);
    cudaGetSymbolAddress((void**)&ff,  g_ff);

    cudaFuncSetAttribute(attn_kernel,
                         cudaFuncAttributeMaxDynamicSharedMemorySize, ATTN_SMEM);

    const dim3 gD  (D_MODEL / 128, N_ROWS / 128);
    const dim3 gFF1(DFF_   / 128, N_ROWS / 128);
    const dim3 gAtt(TSEQ / 64, NHEAD, BATCH);

    // ---- self-attention block ----
    ln_kernel<<<N_ROWS, 256>>>(x, ln1_g, ln1_b, h);
    sgemm_kernel<false, false><<<gD, 256>>>(h, sa_wq, sa_bq, nullptr, q, N_ROWS, D_MODEL, D_MODEL);
    sgemm_kernel<false, false><<<gD, 256>>>(h, sa_wk, sa_bk, nullptr, k, N_ROWS, D_MODEL, D_MODEL);
    sgemm_kernel<false, false><<<gD, 256>>>(h, sa_wv, sa_bv, nullptr, v, N_ROWS, D_MODEL, D_MODEL);
    attn_kernel<<<gAtt, 256, ATTN_SMEM>>>(q, k, v, ctx, 1);
    sgemm_kernel<false, true ><<<gD, 256>>>(ctx, sa_wo, sa_bo, x, x1, N_ROWS, D_MODEL, D_MODEL);

    // ---- cross-attention block ----
    ln_kernel<<<N_ROWS, 256>>>(x1, ln2_g, ln2_b, h);
    sgemm_kernel<false, false><<<gD, 256>>>(h,     ca_wq, ca_bq, nullptr, q, N_ROWS, D_MODEL, D_MODEL);
    sgemm_kernel<false, false><<<gD, 256>>>(src_x, ca_wk, ca_bk, nullptr, k, N_ROWS, D_MODEL, D_MODEL);
    sgemm_kernel<false, false><<<gD, 256>>>(src_x, ca_wv, ca_bv, nullptr, v, N_ROWS, D_MODEL, D_MODEL);
    attn_kernel<<<gAtt, 256, ATTN_SMEM>>>(q, k, v, ctx, 0);
    sgemm_kernel<false, true ><<<gD, 256>>>(ctx, ca_wo, ca_bo, x1, x2, N_ROWS, D_MODEL, D_MODEL);

    // ---- FFN block ----
    ln_kernel<<<N_ROWS, 256>>>(x2, ln3_g, ln3_b, h);
    sgemm_kernel<true,  false><<<gFF1, 256>>>(h,  ff_w1, ff_b1, nullptr, ff, N_ROWS, DFF_,    D_MODEL);
    sgemm_kernel<false, true ><<<gD,   256>>>(ff, ff_w2, ff_b2, x2,      out, N_ROWS, D_MODEL, DFF_);
}

// round 4
// speedup vs baseline: 1.7651x; 1.7651x over previous
#include <cuda_runtime.h>
#include <math.h>

// ---------------------------------------------------------------------------
// SpectroTFDecoder: pre-LN transformer decoder layer, fp32.
// B=4, T=1024, D=1024, H=16, DH=64, DFF=4096.
// Input order: 0 x, 1 src_x, 2 mask, 3 src_mask, 4-9 ln{1,2,3}_{g,b},
// 10-17 weights (sa_wq,sa_wk,sa_wv,sa_wo,ca_wq,ca_wk,ca_wv,ca_wo),
// 18-25 biases (same order), 26-29 ff_w1,ff_b1,ff_w2,ff_b2.
// ---------------------------------------------------------------------------

#define D_MODEL 1024
#define BATCH   4
#define TSEQ    1024
#define N_ROWS  (BATCH * TSEQ)
#define NHEAD   16
#define DHEAD   64
#define DFF_    4096
#define LN_EPS  1e-6f

// Scratch
__device__ float g_h  [N_ROWS * D_MODEL];
__device__ float g_q  [N_ROWS * D_MODEL];
__device__ float g_k  [N_ROWS * D_MODEL];
__device__ float g_v  [N_ROWS * D_MODEL];
__device__ float g_ctx[N_ROWS * D_MODEL];
__device__ float g_x1 [N_ROWS * D_MODEL];
__device__ float g_x2 [N_ROWS * D_MODEL];
__device__ float g_ff [N_ROWS * DFF_];

// ---------------------------------------------------------------------------
// LayerNorm
// ---------------------------------------------------------------------------
__global__ __launch_bounds__(256)
void ln_kernel(const float* __restrict__ x, const float* __restrict__ g,
               const float* __restrict__ bta, float* __restrict__ o)
{
    const int row = blockIdx.x;
    const int t = threadIdx.x;
    const float* xr = x + (size_t)row * D_MODEL;
    float4 xv = *(const float4*)(xr + t * 4);

    float s = xv.x + xv.y + xv.z + xv.w;
    __shared__ float red[8];
    #pragma unroll
    for (int off = 16; off > 0; off >>= 1) s += __shfl_xor_sync(~0u, s, off);
    if ((t & 31) == 0) red[t >> 5] = s;
    __syncthreads();
    float tot = 0.f;
    #pragma unroll
    for (int i = 0; i < 8; i++) tot += red[i];
    const float mu = tot * (1.f / 1024.f);

    const float dx0 = xv.x - mu, dx1 = xv.y - mu, dx2 = xv.z - mu, dx3 = xv.w - mu;
    float sq = dx0*dx0 + dx1*dx1 + dx2*dx2 + dx3*dx3;
    #pragma unroll
    for (int off = 16; off > 0; off >>= 1) sq += __shfl_xor_sync(~0u, sq, off);
    __syncthreads();
    if ((t & 31) == 0) red[t >> 5] = sq;
    __syncthreads();
    float tot2 = 0.f;
    #pragma unroll
    for (int i = 0; i < 8; i++) tot2 += red[i];
    const float sigma = sqrtf(tot2 * (1.f / 1024.f));
    const float inv = 1.f / (sigma + LN_EPS);

    float4 gv = *(const float4*)(g + t * 4);
    float4 bv = *(const float4*)(bta + t * 4);
    float4 ov;
    ov.x = dx0 * inv * gv.x + bv.x;
    ov.y = dx1 * inv * gv.y + bv.y;
    ov.z = dx2 * inv * gv.z + bv.z;
    ov.w = dx3 * inv * gv.w + bv.w;
    *(float4*)(o + (size_t)row * D_MODEL + t * 4) = ov;
}

// ---------------------------------------------------------------------------
// SGEMM (round-2 proven version): C = A@W + bias (+res), optional ReLU.
// 128x128 tile, BK=8, 256 threads, 8x8 micro-tile, double-buffered.
// ---------------------------------------------------------------------------
template<bool RELU, bool RES>
__global__ __launch_bounds__(256, 2)
void sgemm_kernel(const float* __restrict__ A, const float* __restrict__ W,
                  const float* __restrict__ bias, const float* __restrict__ res,
                  float* __restrict__ C, int M, int N, int K)
{
    __shared__ float As[2][8][128];
    __shared__ float Bs[2][8][128];
    const int tid = threadIdx.x;
    const int bm = blockIdx.y * 128;
    const int bn = blockIdx.x * 128;

    const int arow = tid >> 1;
    const int acol = (tid & 1) * 4;
    const int brow = tid >> 5;
    const int bcol = (tid & 31) * 4;

    const float* Aptr = A + (size_t)(bm + arow) * K + acol;
    const float* Bptr = W + (size_t)brow * N + bn + bcol;

    const int ty = tid >> 4;
    const int tx = tid & 15;
    const int crow = ty * 8;
    const int c0 = tx * 4;
    const int c1 = 64 + tx * 4;

    float acc[8][8];
    #pragma unroll
    for (int i = 0; i < 8; i++)
        #pragma unroll
        for (int j = 0; j < 8; j++) acc[i][j] = 0.f;

    {
        float4 a4 = *(const float4*)Aptr;
        float4 b4 = *(const float4*)Bptr;
        As[0][acol + 0][arow] = a4.x;
        As[0][acol + 1][arow] = a4.y;
        As[0][acol + 2][arow] = a4.z;
        As[0][acol + 3][arow] = a4.w;
        *(float4*)&Bs[0][brow][bcol] = b4;
    }
    __syncthreads();

    const int nk = K >> 3;
    for (int kt = 0; kt < nk; kt++) {
        const int cur = kt & 1;
        const int nxt = cur ^ 1;
        float4 a4n, b4n;
        const bool more = (kt + 1 < nk);
        if (more) {
            a4n = *(const float4*)(Aptr + (size_t)(kt + 1) * 8);
            b4n = *(const float4*)(Bptr + (size_t)(kt + 1) * 8 * N);
        }
        #pragma unroll
        for (int k = 0; k < 8; k++) {
            float4 arA = *(const float4*)&As[cur][k][crow];
            float4 arB = *(const float4*)&As[cur][k][crow + 4];
            float4 brA = *(const float4*)&Bs[cur][k][c0];
            float4 brB = *(const float4*)&Bs[cur][k][c1];
            float ar[8] = {arA.x, arA.y, arA.z, arA.w, arB.x, arB.y, arB.z, arB.w};
            float br[8] = {brA.x, brA.y, brA.z, brA.w, brB.x, brB.y, brB.z, brB.w};
            #pragma unroll
            for (int i = 0; i < 8; i++)
                #pragma unroll
                for (int j = 0; j < 8; j++)
                    acc[i][j] += ar[i] * br[j];
        }
        if (more) {
            As[nxt][acol + 0][arow] = a4n.x;
            As[nxt][acol + 1][arow] = a4n.y;
            As[nxt][acol + 2][arow] = a4n.z;
            As[nxt][acol + 3][arow] = a4n.w;
            *(float4*)&Bs[nxt][brow][bcol] = b4n;
        }
        __syncthreads();
    }

    float bia[8];
    #pragma unroll
    for (int j = 0; j < 4; j++) {
        bia[j]     = bias[bn + c0 + j];
        bia[4 + j] = bias[bn + c1 + j];
    }
    #pragma unroll
    for (int i = 0; i < 8; i++) {
        const int row = bm + crow + i;
        float* cp = C + (size_t)row * N + bn;
        float v[8];
        #pragma unroll
        for (int j = 0; j < 8; j++) v[j] = acc[i][j] + bia[j];
        if (RELU) {
            #pragma unroll
            for (int j = 0; j < 8; j++) v[j] = fmaxf(v[j], 0.f);
        }
        if (RES) {
            const float* rp = res + (size_t)row * N + bn;
            float4 r0 = *(const float4*)(rp + c0);
            float4 r1 = *(const float4*)(rp + c1);
            v[0] += r0.x; v[1] += r0.y; v[2] += r0.z; v[3] += r0.w;
            v[4] += r1.x; v[5] += r1.y; v[6] += r1.z; v[7] += r1.w;
        }
        float4 o0 = {v[0], v[1], v[2], v[3]};
        float4 o1 = {v[4], v[5], v[6], v[7]};
        *(float4*)(cp + c0) = o0;
        *(float4*)(cp + c1) = o1;
    }
}

// ---------------------------------------------------------------------------
// Flash attention, register-tiled. Block = 64 q-rows x 1 head x 1 batch.
// 256 threads as 16x16 grid: thread (ty,tx) owns a 4x4 tile:
// rows 4ty..4ty+3, keys/dims 4tx..4tx+3.
// Inner loops: 2x LDS.128 + 16 FMA per k-step (vs 17 LDS + 16 FMA before).
// Smem: Qt (Q^T, scaled), Kt (K^T), Vs (V natural), Pt (P^T). Row stride 68.
// Softmax stats reduced across the 16 tx-lanes with butterfly shuffles.
// ---------------------------------------------------------------------------
#define AST 68
#define ATTN_SMEM (4 * 64 * AST * (int)sizeof(float))

__global__ __launch_bounds__(256)
void attn_kernel(const float* __restrict__ Q, const float* __restrict__ Kv,
                 const float* __restrict__ Vv, float* __restrict__ O,
                 int causal)
{
    const int qt = blockIdx.x;
    const int h  = blockIdx.y;
    const int b  = blockIdx.z;
    const int tid = threadIdx.x;
    const int ty = tid >> 4;
    const int tx = tid & 15;

    const size_t base = ((size_t)b * TSEQ) * D_MODEL + (size_t)h * DHEAD;

    extern __shared__ float sm[];
    float* Qt = sm;                 // [64][AST]  Q transposed (pre-scaled)
    float* Kt = sm + 64 * AST;      // [64][AST]  K transposed
    float* Vs = sm + 2 * 64 * AST;  // [64][AST]  V natural
    float* Pt = sm + 3 * 64 * AST;  // [64][AST]  P transposed

    const int r  = tid >> 2;          // staging row 0..63
    const int cc = (tid & 3) * 16;    // staging dim offset

    // load Q tile, scale, store transposed
    {
        const float* src = Q + base + (size_t)(qt * 64 + r) * D_MODEL + cc;
        #pragma unroll
        for (int c = 0; c < 16; c += 4) {
            float4 v4 = *(const float4*)(src + c);
            Qt[(cc + c + 0) * AST + r] = v4.x * 0.125f;
            Qt[(cc + c + 1) * AST + r] = v4.y * 0.125f;
            Qt[(cc + c + 2) * AST + r] = v4.z * 0.125f;
            Qt[(cc + c + 3) * AST + r] = v4.w * 0.125f;
        }
    }

    float m[4], l[4], acc[4][4];
    #pragma unroll
    for (int i = 0; i < 4; i++) {
        m[i] = -INFINITY; l[i] = 0.f;
        #pragma unroll
        for (int j = 0; j < 4; j++) acc[i][j] = 0.f;
    }

    const int ktEnd = causal ? qt : (TSEQ / 64 - 1);

    for (int kt = 0; kt <= ktEnd; kt++) {
        __syncthreads();   // prior PV reads of Vs/Pt done; Q store visible (1st)
        // stage K transposed + V natural
        {
            const float* ks = Kv + base + (size_t)(kt * 64 + r) * D_MODEL + cc;
            const float* vs = Vv + base + (size_t)(kt * 64 + r) * D_MODEL + cc;
            #pragma unroll
            for (int c = 0; c < 16; c += 4) {
                float4 k4 = *(const float4*)(ks + c);
                Kt[(cc + c + 0) * AST + r] = k4.x;
                Kt[(cc + c + 1) * AST + r] = k4.y;
                Kt[(cc + c + 2) * AST + r] = k4.z;
                Kt[(cc + c + 3) * AST + r] = k4.w;
                float4 v4 = *(const float4*)(vs + c);
                *(float4*)&Vs[r * AST + cc + c] = v4;
            }
        }
        __syncthreads();

        // S tile: 4x4 per thread
        float s[4][4];
        #pragma unroll
        for (int i = 0; i < 4; i++)
            #pragma unroll
            for (int j = 0; j < 4; j++) s[i][j] = 0.f;
        #pragma unroll 4
        for (int dd = 0; dd < 64; dd++) {
            float4 q4 = *(const float4*)&Qt[dd * AST + 4 * ty];
            float4 k4 = *(const float4*)&Kt[dd * AST + 4 * tx];
            float qa[4] = {q4.x, q4.y, q4.z, q4.w};
            float ka[4] = {k4.x, k4.y, k4.z, k4.w};
            #pragma unroll
            for (int i = 0; i < 4; i++)
                #pragma unroll
                for (int j = 0; j < 4; j++)
                    s[i][j] += qa[i] * ka[j];
        }

        // mask + online softmax (per row, reduced over 16 tx-lanes)
        const bool diag = causal && (kt == qt);
        float p[4][4];
        #pragma unroll
        for (int i = 0; i < 4; i++) {
            const int qg = qt * 64 + 4 * ty + i;
            float rmax = -INFINITY;
            #pragma unroll
            for (int j = 0; j < 4; j++) {
                if (diag && (kt * 64 + 4 * tx + j) > qg) s[i][j] = -INFINITY;
                rmax = fmaxf(rmax, s[i][j]);
            }
            rmax = fmaxf(rmax, __shfl_xor_sync(~0u, rmax, 1));
            rmax = fmaxf(rmax, __shfl_xor_sync(~0u, rmax, 2));
            rmax = fmaxf(rmax, __shfl_xor_sync(~0u, rmax, 4));
            rmax = fmaxf(rmax, __shfl_xor_sync(~0u, rmax, 8));
            const float mnew = fmaxf(m[i], rmax);
            const float corr = __expf(m[i] - mnew);
            float rsum = 0.f;
            #pragma unroll
            for (int j = 0; j < 4; j++) {
                p[i][j] = __expf(s[i][j] - mnew);
                rsum += p[i][j];
            }
            rsum += __shfl_xor_sync(~0u, rsum, 1);
            rsum += __shfl_xor_sync(~0u, rsum, 2);
            rsum += __shfl_xor_sync(~0u, rsum, 4);
            rsum += __shfl_xor_sync(~0u, rsum, 8);
            l[i] = l[i] * corr + rsum;
            m[i] = mnew;
            #pragma unroll
            for (int j = 0; j < 4; j++) acc[i][j] *= corr;
        }

        // store P transposed: Pt[key][qrow]
        #pragma unroll
        for (int j = 0; j < 4; j++) {
            float4 pj = {p[0][j], p[1][j], p[2][j], p[3][j]};
            *(float4*)&Pt[(4 * tx + j) * AST + 4 * ty] = pj;
        }
        __syncthreads();

        // O += P @ V
        #pragma unroll 4
        for (int kk = 0; kk < 64; kk++) {
            float4 p4 = *(const float4*)&Pt[kk * AST + 4 * ty];
            float4 v4 = *(const float4*)&Vs[kk * AST + 4 * tx];
            float pa[4] = {p4.x, p4.y, p4.z, p4.w};
            float va[4] = {v4.x, v4.y, v4.z, v4.w};
            #pragma unroll
            for (int i = 0; i < 4; i++)
                #pragma unroll
                for (int j = 0; j < 4; j++)
                    acc[i][j] += pa[i] * va[j];
        }
    }

    // write O
    #pragma unroll
    for (int i = 0; i < 4; i++) {
        const float inv = 1.f / l[i];
        float* op = O + base + (size_t)(qt * 64 + 4 * ty + i) * D_MODEL + 4 * tx;
        float4 o4 = {acc[i][0] * inv, acc[i][1] * inv,
                     acc[i][2] * inv, acc[i][3] * inv};
        *(float4*)op = o4;
    }
}

// ---------------------------------------------------------------------------
// Host orchestration
// ---------------------------------------------------------------------------
extern "C" void kernel_launch(void* const* d_in, const int* in_sizes, int n_in,
                              void* d_out, int out_size)
{
    (void)in_sizes; (void)n_in; (void)out_size;
    const float* x     = (const float*)d_in[0];
    const float* src_x = (const float*)d_in[1];
    const float* ln1_g = (const float*)d_in[4];
    const float* ln1_b = (const float*)d_in[5];
    const float* ln2_g = (const float*)d_in[6];
    const float* ln2_b = (const float*)d_in[7];
    const float* ln3_g = (const float*)d_in[8];
    const float* ln3_b = (const float*)d_in[9];
    const float* sa_wq = (const float*)d_in[10];
    const float* sa_wk = (const float*)d_in[11];
    const float* sa_wv = (const float*)d_in[12];
    const float* sa_wo = (const float*)d_in[13];
    const float* ca_wq = (const float*)d_in[14];
    const float* ca_wk = (const float*)d_in[15];
    const float* ca_wv = (const float*)d_in[16];
    const float* ca_wo = (const float*)d_in[17];
    const float* sa_bq = (const float*)d_in[18];
    const float* sa_bk = (const float*)d_in[19];
    const float* sa_bv = (const float*)d_in[20];
    const float* sa_bo = (const float*)d_in[21];
    const float* ca_bq = (const float*)d_in[22];
    const float* ca_bk = (const float*)d_in[23];
    const float* ca_bv = (const float*)d_in[24];
    const float* ca_bo = (const float*)d_in[25];
    const float* ff_w1 = (const float*)d_in[26];
    const float* ff_b1 = (const float*)d_in[27];
    const float* ff_w2 = (const float*)d_in[28];
    const float* ff_b2 = (const float*)d_in[29];
    float* out = (float*)d_out;

    float *h, *q, *k, *v, *ctx, *x1, *x2, *ff;
    cudaGetSymbolAddress((void**)&h,   g_h);
    cudaGetSymbolAddress((void**)&q,   g_q);
    cudaGetSymbolAddress((void**)&k,   g_k);
    cudaGetSymbolAddress((void**)&v,   g_v);
    cudaGetSymbolAddress((void**)&ctx, g_ctx);
    cudaGetSymbolAddress((void**)&x1,  g_x1);
    cudaGetSymbolAddress((void**)&x2,  g_x2);
    cudaGetSymbolAddress((void**)&ff,  g_ff);

    cudaFuncSetAttribute(attn_kernel,
                         cudaFuncAttributeMaxDynamicSharedMemorySize, ATTN_SMEM);

    const dim3 gD  (D_MODEL / 128, N_ROWS / 128);
    const dim3 gFF1(DFF_   / 128, N_ROWS / 128);
    const dim3 gAtt(TSEQ / 64, NHEAD, BATCH);

    // ---- self-attention block ----
    ln_kernel<<<N_ROWS, 256>>>(x, ln1_g, ln1_b, h);
    sgemm_kernel<false, false><<<gD, 256>>>(h, sa_wq, sa_bq, nullptr, q, N_ROWS, D_MODEL, D_MODEL);
    sgemm_kernel<false, false><<<gD, 256>>>(h, sa_wk, sa_bk, nullptr, k, N_ROWS, D_MODEL, D_MODEL);
    sgemm_kernel<false, false><<<gD, 256>>>(h, sa_wv, sa_bv, nullptr, v, N_ROWS, D_MODEL, D_MODEL);
    attn_kernel<<<gAtt, 256, ATTN_SMEM>>>(q, k, v, ctx, 1);
    sgemm_kernel<false, true ><<<gD, 256>>>(ctx, sa_wo, sa_bo, x, x1, N_ROWS, D_MODEL, D_MODEL);

    // ---- cross-attention block ----
    ln_kernel<<<N_ROWS, 256>>>(x1, ln2_g, ln2_b, h);
    sgemm_kernel<false, false><<<gD, 256>>>(h,     ca_wq, ca_bq, nullptr, q, N_ROWS, D_MODEL, D_MODEL);
    sgemm_kernel<false, false><<<gD, 256>>>(src_x, ca_wk, ca_bk, nullptr, k, N_ROWS, D_MODEL, D_MODEL);
    sgemm_kernel<false, false><<<gD, 256>>>(src_x, ca_wv, ca_bv, nullptr, v, N_ROWS, D_MODEL, D_MODEL);
    attn_kernel<<<gAtt, 256, ATTN_SMEM>>>(q, k, v, ctx, 0);
    sgemm_kernel<false, true ><<<gD, 256>>>(ctx, ca_wo, ca_bo, x1, x2, N_ROWS, D_MODEL, D_MODEL);

    // ---- FFN block ----
    ln_kernel<<<N_ROWS, 256>>>(x2, ln3_g, ln3_b, h);
    sgemm_kernel<true,  false><<<gFF1, 256>>>(h,  ff_w1, ff_b1, nullptr, ff, N_ROWS, DFF_,    D_MODEL);
    sgemm_kernel<false, true ><<<gD,   256>>>(ff, ff_w2, ff_b2, x2,      out, N_ROWS, D_MODEL, DFF_);
}

// round 6
// speedup vs baseline: 2.6977x; 1.5283x over previous
#include <cuda_runtime.h>
#include <cuda_bf16.h>
#include <math.h>
#include <cstdint>

// ---------------------------------------------------------------------------
// SpectroTFDecoder: pre-LN transformer decoder layer, fp32 I/O.
// GEMMs use mma.sync bf16 tensor cores (sm_80-class path, works on plain
// sm_103 target) with hi/lo split (3-MMA compensation) -> fp32-grade accuracy.
// Attention/LN stay SIMT fp32.
// Input order: 0 x, 1 src_x, 2 mask, 3 src_mask, 4-9 ln{1,2,3}_{g,b},
// 10-17 weights (sa_wq,sa_wk,sa_wv,sa_wo,ca_wq,ca_wk,ca_wv,ca_wo),
// 18-25 biases (same order), 26-29 ff_w1,ff_b1,ff_w2,ff_b2.
// ---------------------------------------------------------------------------

#define D_MODEL 1024
#define BATCH   4
#define TSEQ    1024
#define N_ROWS  (BATCH * TSEQ)
#define NHEAD   16
#define DHEAD   64
#define DFF_    4096
#define LN_EPS  1e-6f

// fp32 scratch
__device__ float g_h  [N_ROWS * D_MODEL];
__device__ float g_q  [N_ROWS * D_MODEL];
__device__ float g_k  [N_ROWS * D_MODEL];
__device__ float g_v  [N_ROWS * D_MODEL];
__device__ float g_ctx[N_ROWS * D_MODEL];
__device__ float g_x1 [N_ROWS * D_MODEL];
__device__ float g_x2 [N_ROWS * D_MODEL];
__device__ float g_ff [N_ROWS * DFF_];

// bf16 hi/lo scratch: weights (transposed to [N,K]) and activations
#define WQ_OFF  0
#define WK_OFF  (1 << 20)
#define WV_OFF  (2 << 20)
#define WO_OFF  (3 << 20)
#define CQ_OFF  (4 << 20)
#define CK_OFF  (5 << 20)
#define CV_OFF  (6 << 20)
#define CO_OFF  (7 << 20)
#define W1_OFF  (8 << 20)
#define W2_OFF  (12 << 20)
__device__ __nv_bfloat16 g_whi[16 << 20];
__device__ __nv_bfloat16 g_wlo[16 << 20];
__device__ __nv_bfloat16 g_ahi[16 << 20];
__device__ __nv_bfloat16 g_alo[16 << 20];

// ---------------------------------------------------------------------------
// mma / ldmatrix helpers (sm_80-class, valid on plain sm_103 target)
// ---------------------------------------------------------------------------
__device__ __forceinline__ uint32_t smem_u32(const void* p) {
    uint32_t a;
    asm("{ .reg .u64 t; cvta.to.shared.u64 t, %1; cvt.u32.u64 %0, t; }"
        : "=r"(a) : "l"(p));
    return a;
}

__device__ __forceinline__ void ldm4(uint32_t* r, uint32_t a) {
    asm volatile("ldmatrix.sync.aligned.m8n8.x4.shared.b16 {%0,%1,%2,%3}, [%4];"
                 : "=r"(r[0]), "=r"(r[1]), "=r"(r[2]), "=r"(r[3]) : "r"(a));
}

__device__ __forceinline__ void mma16816(float* c, const uint32_t* a,
                                         const uint32_t* b) {
    asm volatile(
        "mma.sync.aligned.m16n8k16.row.col.f32.bf16.bf16.f32 "
        "{%0,%1,%2,%3},{%4,%5,%6,%7},{%8,%9},{%0,%1,%2,%3};"
        : "+f"(c[0]), "+f"(c[1]), "+f"(c[2]), "+f"(c[3])
        : "r"(a[0]), "r"(a[1]), "r"(a[2]), "r"(a[3]), "r"(b[0]), "r"(b[1]));
}

// ---------------------------------------------------------------------------
// split: fp32 -> bf16 hi + bf16 lo (elementwise). n multiple of 1024.
// ---------------------------------------------------------------------------
__global__ __launch_bounds__(256)
void split_kernel(const float* __restrict__ in, __nv_bfloat16* __restrict__ hi,
                  __nv_bfloat16* __restrict__ lo)
{
    const int i = (blockIdx.x * 256 + threadIdx.x) * 4;
    float4 a = *(const float4*)(in + i);
    float av[4] = {a.x, a.y, a.z, a.w};
    __nv_bfloat16 hv[4], lv[4];
    #pragma unroll
    for (int j = 0; j < 4; j++) {
        hv[j] = __float2bfloat16(av[j]);
        lv[j] = __float2bfloat16(av[j] - __bfloat162float(hv[j]));
    }
    __nv_bfloat162 h01, h23, l01, l23;
    h01.x = hv[0]; h01.y = hv[1]; h23.x = hv[2]; h23.y = hv[3];
    l01.x = lv[0]; l01.y = lv[1]; l23.x = lv[2]; l23.y = lv[3];
    *(__nv_bfloat162*)(hi + i)     = h01;
    *(__nv_bfloat162*)(hi + i + 2) = h23;
    *(__nv_bfloat162*)(lo + i)     = l01;
    *(__nv_bfloat162*)(lo + i + 2) = l23;
}

// ---------------------------------------------------------------------------
// transpose + split: W[K,N] fp32 -> out[N,K] bf16 hi/lo.
// ---------------------------------------------------------------------------
__global__ __launch_bounds__(256)
void tsplit_kernel(const float* __restrict__ W, __nv_bfloat16* __restrict__ hi,
                   __nv_bfloat16* __restrict__ lo, int K, int N)
{
    __shared__ float t[32][33];
    const int x = threadIdx.x & 31;
    const int y = threadIdx.x >> 5;
    const int k0 = blockIdx.y * 32;
    const int n0 = blockIdx.x * 32;
    #pragma unroll
    for (int r = y; r < 32; r += 8)
        t[r][x] = W[(size_t)(k0 + r) * N + n0 + x];
    __syncthreads();
    #pragma unroll
    for (int r = y; r < 32; r += 8) {
        float a = t[x][r];                   // = W[k0+x][n0+r]
        __nv_bfloat16 h = __float2bfloat16(a);
        __nv_bfloat16 l = __float2bfloat16(a - __bfloat162float(h));
        const size_t o = (size_t)(n0 + r) * K + k0 + x;
        hi[o] = h;
        lo[o] = l;
    }
}

// ---------------------------------------------------------------------------
// Tensor-core GEMM: C[M,N] = A@W + bias (+res), optional ReLU.
// A split as Ahi/Alo [M,K] bf16 row-major; B = W^T split as Bhi/Blo [N,K]
// bf16 row-major (exactly the .col B operand layout for mma.sync).
// BM=BN=128, BK=32, 256 threads = 8 warps (2x4), warp tile 64x32.
// 3-MMA hi/lo compensation: Ahi*Bhi + Ahi*Blo + Alo*Bhi, fp32 accum.
// SMEM per stage: 4 tiles of [128][40] bf16 (10240 B each), double-buffered.
// ---------------------------------------------------------------------------
#define TGA_ROW 40                       // padded row stride (bf16 elems)
#define TGA_BYT (128 * TGA_ROW * 2)      // 10240 B per tile
#define TG_STAGE (4 * TGA_BYT)           // 40960 B per stage
#define TC_SMEM (2 * TG_STAGE)           // 81920 B

template<bool RELU, bool RES>
__global__ __launch_bounds__(256, 1)
void tc_gemm(const __nv_bfloat16* __restrict__ Ahi, const __nv_bfloat16* __restrict__ Alo,
             const __nv_bfloat16* __restrict__ Bhi, const __nv_bfloat16* __restrict__ Blo,
             const float* __restrict__ bias, const float* __restrict__ res,
             float* __restrict__ C, int M, int N, int K)
{
    extern __shared__ __align__(128) char dynsmem[];
    const uint32_t sb = smem_u32(dynsmem);
    const int tid = threadIdx.x;
    const int lane = tid & 31;
    const int wid = tid >> 5;
    const int wm = wid >> 2;          // 0..1  (M)
    const int wn = wid & 3;           // 0..3  (N)
    const int bm = blockIdx.y * 128;
    const int bn = blockIdx.x * 128;

    // ---- staging mapping: thread -> (row 0..127, 16-elem half) ----
    const int srow = tid >> 1;
    const int shalf = (tid & 1) * 16;                 // bf16 elems
    const uint32_t so = (uint32_t)(srow * TGA_ROW + shalf) * 2;  // bytes

    const char* gAh = (const char*)(Ahi + (size_t)(bm + srow) * K + shalf);
    const char* gAl = (const char*)(Alo + (size_t)(bm + srow) * K + shalf);
    const char* gBh = (const char*)(Bhi + (size_t)(bn + srow) * K + shalf);
    const char* gBl = (const char*)(Blo + (size_t)(bn + srow) * K + shalf);

    // ---- ldmatrix address offsets (within a stage) ----
    // A: rows = m, cols = k. groups: t0-15 rows m0+lane%16 @k0, t16-31 @k0+8.
    const uint32_t a_off = (uint32_t)((lane & 15) * TGA_ROW * 2 + (lane >> 4) * 16);
    // B: rows = n, cols = k. n = ng*16 + (lane>>4)*8 + lane%8 ; k = ((lane>>3)&1)*8.
    const uint32_t b_off = (uint32_t)((((lane >> 4) << 3) + (lane & 7)) * TGA_ROW * 2
                                      + ((lane >> 3) & 1) * 16);

    uint32_t aAddr[4], bAddr[2];   // per m-tile / n-group, stage 0, hi tile
    #pragma unroll
    for (int mt = 0; mt < 4; mt++)
        aAddr[mt] = sb + (uint32_t)((wm * 64 + mt * 16) * TGA_ROW * 2) + a_off;
    #pragma unroll
    for (int ng = 0; ng < 2; ng++)
        bAddr[ng] = sb + 2 * TGA_BYT + (uint32_t)((wn * 32 + ng * 16) * TGA_ROW * 2) + b_off;

    float acc[4][4][4];
    #pragma unroll
    for (int mt = 0; mt < 4; mt++)
        #pragma unroll
        for (int nt = 0; nt < 4; nt++)
            #pragma unroll
            for (int r = 0; r < 4; r++) acc[mt][nt][r] = 0.f;

    // ---- prologue: stage 0 ----
    {
        char* t = dynsmem;
        *(uint4*)(t + so)                = *(const uint4*)gAh;
        *(uint4*)(t + so + 16)           = *(const uint4*)(gAh + 16);
        *(uint4*)(t + TGA_BYT + so)      = *(const uint4*)gAl;
        *(uint4*)(t + TGA_BYT + so + 16) = *(const uint4*)(gAl + 16);
        *(uint4*)(t + 2*TGA_BYT + so)       = *(const uint4*)gBh;
        *(uint4*)(t + 2*TGA_BYT + so + 16)  = *(const uint4*)(gBh + 16);
        *(uint4*)(t + 3*TGA_BYT + so)       = *(const uint4*)gBl;
        *(uint4*)(t + 3*TGA_BYT + so + 16)  = *(const uint4*)(gBl + 16);
    }
    __syncthreads();

    const int nk = K >> 5;     // BK = 32
    for (int kt = 0; kt < nk; kt++) {
        const int cur = kt & 1;
        const int nxt = cur ^ 1;
        const bool more = (kt + 1 < nk);
        uint4 pa0, pa1, pl0, pl1, pb0, pb1, pq0, pq1;
        if (more) {
            const int gb = (kt + 1) * 64;    // 32 elems * 2B
            pa0 = *(const uint4*)(gAh + gb);
            pa1 = *(const uint4*)(gAh + gb + 16);
            pl0 = *(const uint4*)(gAl + gb);
            pl1 = *(const uint4*)(gAl + gb + 16);
            pb0 = *(const uint4*)(gBh + gb);
            pb1 = *(const uint4*)(gBh + gb + 16);
            pq0 = *(const uint4*)(gBl + gb);
            pq1 = *(const uint4*)(gBl + gb + 16);
        }

        const uint32_t stg = (uint32_t)cur * TG_STAGE;
        #pragma unroll
        for (int ks = 0; ks < 2; ks++) {
            const uint32_t kb = stg + ks * 32;   // 16 elems * 2B
            uint32_t ah[4][4], al[4][4], bh[2][4], bl[2][4];
            #pragma unroll
            for (int mt = 0; mt < 4; mt++) {
                ldm4(ah[mt], aAddr[mt] + kb);
                ldm4(al[mt], aAddr[mt] + TGA_BYT + kb);
            }
            #pragma unroll
            for (int ng = 0; ng < 2; ng++) {
                ldm4(bh[ng], bAddr[ng] + kb);
                ldm4(bl[ng], bAddr[ng] + TGA_BYT + kb);
            }
            #pragma unroll
            for (int mt = 0; mt < 4; mt++) {
                #pragma unroll
                for (int nt = 0; nt < 4; nt++) {
                    const int ng = nt >> 1;
                    const int hf = (nt & 1) * 2;
                    mma16816(acc[mt][nt], ah[mt], &bh[ng][hf]);
                    mma16816(acc[mt][nt], ah[mt], &bl[ng][hf]);
                    mma16816(acc[mt][nt], al[mt], &bh[ng][hf]);
                }
            }
        }

        if (more) {
            char* t = dynsmem + nxt * TG_STAGE;
            *(uint4*)(t + so)                = pa0;
            *(uint4*)(t + so + 16)           = pa1;
            *(uint4*)(t + TGA_BYT + so)      = pl0;
            *(uint4*)(t + TGA_BYT + so + 16) = pl1;
            *(uint4*)(t + 2*TGA_BYT + so)       = pb0;
            *(uint4*)(t + 2*TGA_BYT + so + 16)  = pb1;
            *(uint4*)(t + 3*TGA_BYT + so)       = pq0;
            *(uint4*)(t + 3*TGA_BYT + so + 16)  = pq1;
        }
        __syncthreads();
    }

    // ---- epilogue ----
    // acc[mt][nt]: c0,c1 -> (row m0+lane/4, col n0+(lane%4)*2 +0/1)
    //              c2,c3 -> row +8.
    const int er = lane >> 2;
    const int ec = (lane & 3) * 2;
    #pragma unroll
    for (int mt = 0; mt < 4; mt++) {
        const int row0 = bm + wm * 64 + mt * 16 + er;
        #pragma unroll
        for (int nt = 0; nt < 4; nt++) {
            const int col = bn + wn * 32 + nt * 8 + ec;
            float2 bv = *(const float2*)(bias + col);
            float v0 = acc[mt][nt][0] + bv.x;
            float v1 = acc[mt][nt][1] + bv.y;
            float v2 = acc[mt][nt][2] + bv.x;
            float v3 = acc[mt][nt][3] + bv.y;
            if (RELU) {
                v0 = fmaxf(v0, 0.f); v1 = fmaxf(v1, 0.f);
                v2 = fmaxf(v2, 0.f); v3 = fmaxf(v3, 0.f);
            }
            if (RES) {
                float2 r0 = *(const float2*)(res + (size_t)row0 * N + col);
                float2 r1 = *(const float2*)(res + (size_t)(row0 + 8) * N + col);
                v0 += r0.x; v1 += r0.y; v2 += r1.x; v3 += r1.y;
            }
            float2 o0 = {v0, v1};
            float2 o1 = {v2, v3};
            *(float2*)(C + (size_t)row0 * N + col) = o0;
            *(float2*)(C + (size_t)(row0 + 8) * N + col) = o1;
        }
    }
}

// ---------------------------------------------------------------------------
// LayerNorm
// ---------------------------------------------------------------------------
__global__ __launch_bounds__(256)
void ln_kernel(const float* __restrict__ x, const float* __restrict__ g,
               const float* __restrict__ bta, float* __restrict__ o)
{
    const int row = blockIdx.x;
    const int t = threadIdx.x;
    const float* xr = x + (size_t)row * D_MODEL;
    float4 xv = *(const float4*)(xr + t * 4);

    float s = xv.x + xv.y + xv.z + xv.w;
    __shared__ float red[8];
    #pragma unroll
    for (int off = 16; off > 0; off >>= 1) s += __shfl_xor_sync(~0u, s, off);
    if ((t & 31) == 0) red[t >> 5] = s;
    __syncthreads();
    float tot = 0.f;
    #pragma unroll
    for (int i = 0; i < 8; i++) tot += red[i];
    const float mu = tot * (1.f / 1024.f);

    const float dx0 = xv.x - mu, dx1 = xv.y - mu, dx2 = xv.z - mu, dx3 = xv.w - mu;
    float sq = dx0*dx0 + dx1*dx1 + dx2*dx2 + dx3*dx3;
    #pragma unroll
    for (int off = 16; off > 0; off >>= 1) sq += __shfl_xor_sync(~0u, sq, off);
    __syncthreads();
    if ((t & 31) == 0) red[t >> 5] = sq;
    __syncthreads();
    float tot2 = 0.f;
    #pragma unroll
    for (int i = 0; i < 8; i++) tot2 += red[i];
    const float sigma = sqrtf(tot2 * (1.f / 1024.f));
    const float inv = 1.f / (sigma + LN_EPS);

    float4 gv = *(const float4*)(g + t * 4);
    float4 bv = *(const float4*)(bta + t * 4);
    float4 ov;
    ov.x = dx0 * inv * gv.x + bv.x;
    ov.y = dx1 * inv * gv.y + bv.y;
    ov.z = dx2 * inv * gv.z + bv.z;
    ov.w = dx3 * inv * gv.w + bv.w;
    *(float4*)(o + (size_t)row * D_MODEL + t * 4) = ov;
}

// ---------------------------------------------------------------------------
// Flash attention (round-4 register-tiled version, unchanged).
// ---------------------------------------------------------------------------
#define AST 68
#define ATTN_SMEM (4 * 64 * AST * (int)sizeof(float))

__global__ __launch_bounds__(256)
void attn_kernel(const float* __restrict__ Q, const float* __restrict__ Kv,
                 const float* __restrict__ Vv, float* __restrict__ O,
                 int causal)
{
    const int qt = blockIdx.x;
    const int h  = blockIdx.y;
    const int b  = blockIdx.z;
    const int tid = threadIdx.x;
    const int ty = tid >> 4;
    const int tx = tid & 15;

    const size_t base = ((size_t)b * TSEQ) * D_MODEL + (size_t)h * DHEAD;

    extern __shared__ __align__(128) char dynsmem[];
    float* sm = (float*)dynsmem;
    float* Qt = sm;
    float* Kt = sm + 64 * AST;
    float* Vs = sm + 2 * 64 * AST;
    float* Pt = sm + 3 * 64 * AST;

    const int r  = tid >> 2;
    const int cc = (tid & 3) * 16;

    {
        const float* src = Q + base + (size_t)(qt * 64 + r) * D_MODEL + cc;
        #pragma unroll
        for (int c = 0; c < 16; c += 4) {
            float4 v4 = *(const float4*)(src + c);
            Qt[(cc + c + 0) * AST + r] = v4.x * 0.125f;
            Qt[(cc + c + 1) * AST + r] = v4.y * 0.125f;
            Qt[(cc + c + 2) * AST + r] = v4.z * 0.125f;
            Qt[(cc + c + 3) * AST + r] = v4.w * 0.125f;
        }
    }

    float m[4], l[4], acc[4][4];
    #pragma unroll
    for (int i = 0; i < 4; i++) {
        m[i] = -INFINITY; l[i] = 0.f;
        #pragma unroll
        for (int j = 0; j < 4; j++) acc[i][j] = 0.f;
    }

    const int ktEnd = causal ? qt : (TSEQ / 64 - 1);

    for (int kt = 0; kt <= ktEnd; kt++) {
        __syncthreads();
        {
            const float* ks = Kv + base + (size_t)(kt * 64 + r) * D_MODEL + cc;
            const float* vs = Vv + base + (size_t)(kt * 64 + r) * D_MODEL + cc;
            #pragma unroll
            for (int c = 0; c < 16; c += 4) {
                float4 k4 = *(const float4*)(ks + c);
                Kt[(cc + c + 0) * AST + r] = k4.x;
                Kt[(cc + c + 1) * AST + r] = k4.y;
                Kt[(cc + c + 2) * AST + r] = k4.z;
                Kt[(cc + c + 3) * AST + r] = k4.w;
                float4 v4 = *(const float4*)(vs + c);
                *(float4*)&Vs[r * AST + cc + c] = v4;
            }
        }
        __syncthreads();

        float s[4][4];
        #pragma unroll
        for (int i = 0; i < 4; i++)
            #pragma unroll
            for (int j = 0; j < 4; j++) s[i][j] = 0.f;
        #pragma unroll 4
        for (int dd = 0; dd < 64; dd++) {
            float4 q4 = *(const float4*)&Qt[dd * AST + 4 * ty];
            float4 k4 = *(const float4*)&Kt[dd * AST + 4 * tx];
            float qa[4] = {q4.x, q4.y, q4.z, q4.w};
            float ka[4] = {k4.x, k4.y, k4.z, k4.w};
            #pragma unroll
            for (int i = 0; i < 4; i++)
                #pragma unroll
                for (int j = 0; j < 4; j++)
                    s[i][j] += qa[i] * ka[j];
        }

        const bool diag = causal && (kt == qt);
        float p[4][4];
        #pragma unroll
        for (int i = 0; i < 4; i++) {
            const int qg = qt * 64 + 4 * ty + i;
            float rmax = -INFINITY;
            #pragma unroll
            for (int j = 0; j < 4; j++) {
                if (diag && (kt * 64 + 4 * tx + j) > qg) s[i][j] = -INFINITY;
                rmax = fmaxf(rmax, s[i][j]);
            }
            rmax = fmaxf(rmax, __shfl_xor_sync(~0u, rmax, 1));
            rmax = fmaxf(rmax, __shfl_xor_sync(~0u, rmax, 2));
            rmax = fmaxf(rmax, __shfl_xor_sync(~0u, rmax, 4));
            rmax = fmaxf(rmax, __shfl_xor_sync(~0u, rmax, 8));
            const float mnew = fmaxf(m[i], rmax);
            const float corr = __expf(m[i] - mnew);
            float rsum = 0.f;
            #pragma unroll
            for (int j = 0; j < 4; j++) {
                p[i][j] = __expf(s[i][j] - mnew);
                rsum += p[i][j];
            }
            rsum += __shfl_xor_sync(~0u, rsum, 1);
            rsum += __shfl_xor_sync(~0u, rsum, 2);
            rsum += __shfl_xor_sync(~0u, rsum, 4);
            rsum += __shfl_xor_sync(~0u, rsum, 8);
            l[i] = l[i] * corr + rsum;
            m[i] = mnew;
            #pragma unroll
            for (int j = 0; j < 4; j++) acc[i][j] *= corr;
        }

        #pragma unroll
        for (int j = 0; j < 4; j++) {
            float4 pj = {p[0][j], p[1][j], p[2][j], p[3][j]};
            *(float4*)&Pt[(4 * tx + j) * AST + 4 * ty] = pj;
        }
        __syncthreads();

        #pragma unroll 4
        for (int kk = 0; kk < 64; kk++) {
            float4 p4 = *(const float4*)&Pt[kk * AST + 4 * ty];
            float4 v4 = *(const float4*)&Vs[kk * AST + 4 * tx];
            float pa[4] = {p4.x, p4.y, p4.z, p4.w};
            float va[4] = {v4.x, v4.y, v4.z, v4.w};
            #pragma unroll
            for (int i = 0; i < 4; i++)
                #pragma unroll
                for (int j = 0; j < 4; j++)
                    acc[i][j] += pa[i] * va[j];
        }
    }

    #pragma unroll
    for (int i = 0; i < 4; i++) {
        const float inv = 1.f / l[i];
        float* op = O + base + (size_t)(qt * 64 + 4 * ty + i) * D_MODEL + 4 * tx;
        float4 o4 = {acc[i][0] * inv, acc[i][1] * inv,
                     acc[i][2] * inv, acc[i][3] * inv};
        *(float4*)op = o4;
    }
}

// ---------------------------------------------------------------------------
// Host orchestration
// ---------------------------------------------------------------------------
extern "C" void kernel_launch(void* const* d_in, const int* in_sizes, int n_in,
                              void* d_out, int out_size)
{
    (void)in_sizes; (void)n_in; (void)out_size;
    const float* x     = (const float*)d_in[0];
    const float* src_x = (const float*)d_in[1];
    const float* ln1_g = (const float*)d_in[4];
    const float* ln1_b = (const float*)d_in[5];
    const float* ln2_g = (const float*)d_in[6];
    const float* ln2_b = (const float*)d_in[7];
    const float* ln3_g = (const float*)d_in[8];
    const float* ln3_b = (const float*)d_in[9];
    const float* W[8];
    for (int i = 0; i < 8; i++) W[i] = (const float*)d_in[10 + i];
    const float* Bv[8];
    for (int i = 0; i < 8; i++) Bv[i] = (const float*)d_in[18 + i];
    const float* ff_w1 = (const float*)d_in[26];
    const float* ff_b1 = (const float*)d_in[27];
    const float* ff_w2 = (const float*)d_in[28];
    const float* ff_b2 = (const float*)d_in[29];
    float* out = (float*)d_out;

    float *h, *q, *k, *v, *ctx, *x1, *x2, *ff;
    cudaGetSymbolAddress((void**)&h,   g_h);
    cudaGetSymbolAddress((void**)&q,   g_q);
    cudaGetSymbolAddress((void**)&k,   g_k);
    cudaGetSymbolAddress((void**)&v,   g_v);
    cudaGetSymbolAddress((void**)&ctx, g_ctx);
    cudaGetSymbolAddress((void**)&x1,  g_x1);
    cudaGetSymbolAddress((void**)&x2,  g_x2);
    cudaGetSymbolAddress((void**)&ff,  g_ff);
    __nv_bfloat16 *whi, *wlo, *ahi, *alo;
    cudaGetSymbolAddress((void**)&whi, g_whi);
    cudaGetSymbolAddress((void**)&wlo, g_wlo);
    cudaGetSymbolAddress((void**)&ahi, g_ahi);
    cudaGetSymbolAddress((void**)&alo, g_alo);

    cudaFuncSetAttribute(attn_kernel,
                         cudaFuncAttributeMaxDynamicSharedMemorySize, ATTN_SMEM);
    cudaFuncSetAttribute(tc_gemm<false, false>,
                         cudaFuncAttributeMaxDynamicSharedMemorySize, TC_SMEM);
    cudaFuncSetAttribute(tc_gemm<false, true>,
                         cudaFuncAttributeMaxDynamicSharedMemorySize, TC_SMEM);
    cudaFuncSetAttribute(tc_gemm<true, false>,
                         cudaFuncAttributeMaxDynamicSharedMemorySize, TC_SMEM);

    const int WOFF[8] = {WQ_OFF, WK_OFF, WV_OFF, WO_OFF, CQ_OFF, CK_OFF, CV_OFF, CO_OFF};

    // ---- weight prep: transpose + split ----
    {
        dim3 gsq(D_MODEL / 32, D_MODEL / 32);
        for (int i = 0; i < 8; i++)
            tsplit_kernel<<<gsq, 256>>>(W[i], whi + WOFF[i], wlo + WOFF[i], D_MODEL, D_MODEL);
        dim3 g1(DFF_ / 32, D_MODEL / 32);   // ff_w1 [1024,4096] -> [4096,1024]
        tsplit_kernel<<<g1, 256>>>(ff_w1, whi + W1_OFF, wlo + W1_OFF, D_MODEL, DFF_);
        dim3 g2(D_MODEL / 32, DFF_ / 32);   // ff_w2 [4096,1024] -> [1024,4096]
        tsplit_kernel<<<g2, 256>>>(ff_w2, whi + W2_OFF, wlo + W2_OFF, DFF_, D_MODEL);
    }

    const int nElemD = N_ROWS * D_MODEL;       // 4M
    const int nElemF = N_ROWS * DFF_;          // 16M
    const dim3 gD (D_MODEL / 128, N_ROWS / 128);   // (8, 32)
    const dim3 gF1(DFF_   / 128, N_ROWS / 128);    // (32, 32)
    const dim3 gAtt(TSEQ / 64, NHEAD, BATCH);

    // ---- self-attention block ----
    ln_kernel<<<N_ROWS, 256>>>(x, ln1_g, ln1_b, h);
    split_kernel<<<nElemD / 1024, 256>>>(h, ahi, alo);
    tc_gemm<false, false><<<gD, 256, TC_SMEM>>>(ahi, alo, whi + WQ_OFF, wlo + WQ_OFF, Bv[0], nullptr, q, N_ROWS, D_MODEL, D_MODEL);
    tc_gemm<false, false><<<gD, 256, TC_SMEM>>>(ahi, alo, whi + WK_OFF, wlo + WK_OFF, Bv[1], nullptr, k, N_ROWS, D_MODEL, D_MODEL);
    tc_gemm<false, false><<<gD, 256, TC_SMEM>>>(ahi, alo, whi + WV_OFF, wlo + WV_OFF, Bv[2], nullptr, v, N_ROWS, D_MODEL, D_MODEL);
    attn_kernel<<<gAtt, 256, ATTN_SMEM>>>(q, k, v, ctx, 1);
    split_kernel<<<nElemD / 1024, 256>>>(ctx, ahi, alo);
    tc_gemm<false, true ><<<gD, 256, TC_SMEM>>>(ahi, alo, whi + WO_OFF, wlo + WO_OFF, Bv[3], x, x1, N_ROWS, D_MODEL, D_MODEL);

    // ---- cross-attention block ----
    ln_kernel<<<N_ROWS, 256>>>(x1, ln2_g, ln2_b, h);
    split_kernel<<<nElemD / 1024, 256>>>(h, ahi, alo);
    tc_gemm<false, false><<<gD, 256, TC_SMEM>>>(ahi, alo, whi + CQ_OFF, wlo + CQ_OFF, Bv[4], nullptr, q, N_ROWS, D_MODEL, D_MODEL);
    split_kernel<<<nElemD / 1024, 256>>>(src_x, ahi, alo);
    tc_gemm<false, false><<<gD, 256, TC_SMEM>>>(ahi, alo, whi + CK_OFF, wlo + CK_OFF, Bv[5], nullptr, k, N_ROWS, D_MODEL, D_MODEL);
    tc_gemm<false, false><<<gD, 256, TC_SMEM>>>(ahi, alo, whi + CV_OFF, wlo + CV_OFF, Bv[6], nullptr, v, N_ROWS, D_MODEL, D_MODEL);
    attn_kernel<<<gAtt, 256, ATTN_SMEM>>>(q, k, v, ctx, 0);
    split_kernel<<<nElemD / 1024, 256>>>(ctx, ahi, alo);
    tc_gemm<false, true ><<<gD, 256, TC_SMEM>>>(ahi, alo, whi + CO_OFF, wlo + CO_OFF, Bv[7], x1, x2, N_ROWS, D_MODEL, D_MODEL);

    // ---- FFN block ----
    ln_kernel<<<N_ROWS, 256>>>(x2, ln3_g, ln3_b, h);
    split_kernel<<<nElemD / 1024, 256>>>(h, ahi, alo);
    tc_gemm<true,  false><<<gF1, 256, TC_SMEM>>>(ahi, alo, whi + W1_OFF, wlo + W1_OFF, ff_b1, nullptr, ff, N_ROWS, DFF_, D_MODEL);
    split_kernel<<<nElemF / 1024, 256>>>(ff, ahi, alo);
    tc_gemm<false, true ><<<gD, 256, TC_SMEM>>>(ahi, alo, whi + W2_OFF, wlo + W2_OFF, ff_b2, x2, out, N_ROWS, D_MODEL, DFF_);
}